// round 1
// baseline (speedup 1.0000x reference)
#include <cuda_runtime.h>

// LatentDT: z = clamp(path-min of signed dot products down a depth-10 binary tree, 0, 1)
// Closed form: z[n, v] = clamp(min(1, min_{(s,dir) on path root->v} dir * <x[n], A[s]>), 0, 1)
// Pruning: if path-min <= 0 at any node, entire subtree clamps to 0 -> skip it.
// Expected active nodes per row ~ DEPTH+1, so the kernel is output-bandwidth bound.

#define DEPTH     10
#define NB_SPLIT  1023   // 2^10 - 1
#define NB_NODES  2047   // 2^11 - 1
#define KDIM      128

__global__ void __launch_bounds__(256, 8) latentdt_kernel(
    const float* __restrict__ x,
    const float* __restrict__ A,
    float* __restrict__ out,
    int rows)
{
    const int warp_global = (blockIdx.x * blockDim.x + threadIdx.x) >> 5;
    const int lane = threadIdx.x & 31;
    if (warp_global >= rows) return;

    // Load this row of x: 128 floats, 4 per lane (512B, coalesced, aligned).
    const float4 xv = __ldg(reinterpret_cast<const float4*>(
                                x + (size_t)warp_global * KDIM) + lane);

    float* outrow = out + (size_t)warp_global * NB_NODES;

    // Zero-fill the output row (coalesced; 64 iterations of 128B per warp).
    for (int idx = lane; idx < NB_NODES; idx += 32) {
        outrow[idx] = 0.0f;
    }
    __syncwarp();               // order fill stores before lane-0 scatter stores
    if (lane == 0) outrow[0] = 1.0f;   // root: clamp(1) = 1

    // Warp-uniform DFS over splits with positive path-min.
    // All per-iteration values (q, reduced dot) are identical across lanes,
    // so every lane redundantly keeps the same small stack (no sync needed).
    int   st_node[DEPTH + 2];
    float st_q[DEPTH + 2];
    int   sp   = 0;
    int   node = 0;
    float q    = 1.0f;

    while (true) {
        // dot(x_row, A[node]) : float4 per lane + butterfly reduce
        const float4 av = __ldg(reinterpret_cast<const float4*>(
                                    A + (size_t)node * KDIM) + lane);
        float p = fmaf(xv.x, av.x,
                  fmaf(xv.y, av.y,
                  fmaf(xv.z, av.z, xv.w * av.w)));
        p += __shfl_xor_sync(0xffffffffu, p, 16);
        p += __shfl_xor_sync(0xffffffffu, p, 8);
        p += __shfl_xor_sync(0xffffffffu, p, 4);
        p += __shfl_xor_sync(0xffffffffu, p, 2);
        p += __shfl_xor_sync(0xffffffffu, p, 1);
        // p is now warp-uniform.

        const float qL = fminf(q, p);
        const float qR = fminf(q, -p);
        const int cl = 2 * node + 1;     // left child (cl+1 = right child)

        if (lane == 0) {
            if (qL > 0.0f) outrow[cl]     = fminf(qL, 1.0f);
            if (qR > 0.0f) outrow[cl + 1] = fminf(qR, 1.0f);
        }

        // Recurse only into split-node children (cl < NB_SPLIT covers both:
        // cl is odd, so cl < 1023 <=> cl+1 < 1023) with positive path-min.
        const bool childIsSplit = (cl < NB_SPLIT);
        const bool goL = childIsSplit && (qL > 0.0f);
        const bool goR = childIsSplit && (qR > 0.0f);

        if (goL) {
            if (goR) { st_node[sp] = cl + 1; st_q[sp] = qR; ++sp; }
            node = cl;  q = qL;
        } else if (goR) {
            node = cl + 1;  q = qR;
        } else {
            if (sp == 0) break;
            --sp;
            node = st_node[sp];  q = st_q[sp];
        }
    }
}

extern "C" void kernel_launch(void* const* d_in, const int* in_sizes, int n_in,
                              void* d_out, int out_size)
{
    const float* x = (const float*)d_in[0];   // [rows, 128]
    const float* A = (const float*)d_in[1];   // [1023, 128]
    float* out = (float*)d_out;               // [rows, 2047]

    const int rows = out_size / NB_NODES;     // 32768

    const int threads = 256;                  // 8 warps/block, 1 row/warp
    const int warps_per_block = threads / 32;
    const int blocks = (rows + warps_per_block - 1) / warps_per_block;

    latentdt_kernel<<<blocks, threads>>>(x, A, out, rows);
}